// round 2
// baseline (speedup 1.0000x reference)
#include <cuda_runtime.h>

// Problem constants
#define Bn   64
#define Tn   2048
#define In   32
#define Hn   256
#define On   32

// Parallel decomposition
#define NB   16      // batch groups (independent)
#define NG   8       // CTAs per group (share h via L2 + group barrier)
#define BPG  4       // batches per group
#define UPC  32      // hidden units per CTA
#define JPC  128     // gate rows per CTA (4 gates x 32 units)
#define Kn   288     // K = H + I (fused [h, x] vector)
#define KP   292     // padded K (bank-conflict-free: 292 % 32 = 4)
#define NTHR 256

#define FCROWS 32

// Scratch (allocation-free rule: __device__ globals)
__device__ float    g_hbuf[2][Bn][Hn];                 // double-buffered h exchange
__device__ float    g_hout[(size_t)Bn * Tn * Hn];      // h history for FC (134 MB)
__device__ unsigned g_bar[NB * 32];                    // per-group barrier counters, 128B apart

static __device__ __forceinline__ unsigned ld_acq(const unsigned* p) {
    unsigned v;
    asm volatile("ld.global.acquire.gpu.u32 %0, [%1];" : "=r"(v) : "l"(p));
    return v;
}
static __device__ __forceinline__ float sigm(float xv) {
    return 1.0f / (1.0f + __expf(-xv));
}
static __device__ __forceinline__ float tanh_fast(float xv) {
    xv = fminf(fmaxf(xv, -15.0f), 15.0f);   // avoid inf/inf
    float e = __expf(2.0f * xv);
    return __fdividef(e - 1.0f, e + 1.0f);
}

__global__ void reset_kernel() {
    int i = blockIdx.x * blockDim.x + threadIdx.x;
    if (i < NB * 32) g_bar[i] = 0u;
}

// Persistent LSTM kernel: 128 CTAs (16 groups x 8), 1 CTA/SM, all co-resident.
__global__ void __launch_bounds__(NTHR, 1) lstm_kernel(
    const float* __restrict__ x,
    const float* __restrict__ W_ih,
    const float* __restrict__ W_hh,
    const float* __restrict__ b_ih,
    const float* __restrict__ b_hh)
{
    extern __shared__ float smem[];
    float* sW    = smem;                      // [JPC][KP]
    float* sV    = sW + JPC * KP;             // [BPG][KP]  = [h(256) | x(32) | pad(4)]
    float* sGate = sV + BPG * KP;             // [4][BPG][UPC]
    float* sC    = sGate + 4 * BPG * UPC;     // [BPG][UPC]
    float* sBias = sC + BPG * UPC;            // [JPC]

    const int tid   = threadIdx.x;
    const int group = blockIdx.x / NG;
    const int slot  = blockIdx.x % NG;
    const int b0    = group * BPG;
    const int u0    = slot * UPC;

    // ---- one-time setup: W slice, bias, zero h/c, x(t=0) ----
    for (int idx = tid; idx < JPC * Kn; idx += NTHR) {
        int j = idx / Kn;
        int k = idx - j * Kn;
        int gate = j >> 5;
        int u    = j & 31;
        int row  = gate * Hn + u0 + u;        // PyTorch gate order i,f,g,o
        float w  = (k < Hn) ? W_hh[row * Hn + k] : W_ih[row * In + (k - Hn)];
        sW[j * KP + k] = w;
    }
    for (int j = tid; j < JPC; j += NTHR) {
        int gate = j >> 5, u = j & 31;
        int row = gate * Hn + u0 + u;
        sBias[j] = b_ih[row] + b_hh[row];
    }
    for (int idx = tid; idx < BPG * KP; idx += NTHR) sV[idx] = 0.0f;
    for (int idx = tid; idx < BPG * UPC; idx += NTHR) sC[idx] = 0.0f;
    __syncthreads();
    if (tid < BPG * In) {
        int bb = tid / In, i = tid % In;
        sV[bb * KP + Hn + i] = x[((size_t)(b0 + bb) * Tn) * In + i];
    }
    __syncthreads();

    unsigned* barp = &g_bar[group * 32];
    const int j = tid;                                   // gate row (GEMM threads: tid < 128)
    const float bias_j = (tid < JPC) ? sBias[j] : 0.0f;

    for (int t = 0; t < Tn; ++t) {
        // ---- gate GEMM: warps 0-3, lane = gate row, 4 batch accumulators ----
        if (tid < JPC) {
            float a0 = bias_j, a1 = bias_j, a2 = bias_j, a3 = bias_j;
            const float4* wr = (const float4*)(sW + j * KP);
            const float4* v0 = (const float4*)(sV);
            const float4* v1 = (const float4*)(sV + KP);
            const float4* v2 = (const float4*)(sV + 2 * KP);
            const float4* v3 = (const float4*)(sV + 3 * KP);
#pragma unroll 4
            for (int kk = 0; kk < Kn / 4; ++kk) {
                float4 w4 = wr[kk];
                float4 p0 = v0[kk], p1 = v1[kk], p2 = v2[kk], p3 = v3[kk];
                a0 = fmaf(w4.x, p0.x, a0); a0 = fmaf(w4.y, p0.y, a0);
                a0 = fmaf(w4.z, p0.z, a0); a0 = fmaf(w4.w, p0.w, a0);
                a1 = fmaf(w4.x, p1.x, a1); a1 = fmaf(w4.y, p1.y, a1);
                a1 = fmaf(w4.z, p1.z, a1); a1 = fmaf(w4.w, p1.w, a1);
                a2 = fmaf(w4.x, p2.x, a2); a2 = fmaf(w4.y, p2.y, a2);
                a2 = fmaf(w4.z, p2.z, a2); a2 = fmaf(w4.w, p2.w, a2);
                a3 = fmaf(w4.x, p3.x, a3); a3 = fmaf(w4.y, p3.y, a3);
                a3 = fmaf(w4.z, p3.z, a3); a3 = fmaf(w4.w, p3.w, a3);
            }
            // activations (gate uniform per warp: warp w == gate w)
            int gate = j >> 5;
            int u    = j & 31;
            float r0, r1, r2, r3;
            if (gate == 2) {                      // g: tanh
                r0 = tanh_fast(a0); r1 = tanh_fast(a1);
                r2 = tanh_fast(a2); r3 = tanh_fast(a3);
            } else {                              // i, f, o: sigmoid
                r0 = sigm(a0); r1 = sigm(a1); r2 = sigm(a2); r3 = sigm(a3);
            }
            sGate[(gate * BPG + 0) * UPC + u] = r0;
            sGate[(gate * BPG + 1) * UPC + u] = r1;
            sGate[(gate * BPG + 2) * UPC + u] = r2;
            sGate[(gate * BPG + 3) * UPC + u] = r3;
        }
        __syncthreads();

        // ---- c/h update + publish h slice ----
        if (tid < BPG * UPC) {
            int bb = tid >> 5, u = tid & 31;
            float iv = sGate[(0 * BPG + bb) * UPC + u];
            float fv = sGate[(1 * BPG + bb) * UPC + u];
            float gv = sGate[(2 * BPG + bb) * UPC + u];
            float ov = sGate[(3 * BPG + bb) * UPC + u];
            float c  = fmaf(fv, sC[bb * UPC + u], iv * gv);
            sC[bb * UPC + u] = c;
            float h  = ov * tanh_fast(c);
            int bg = b0 + bb, ug = u0 + u;
            g_hbuf[t & 1][bg][ug] = h;
            g_hout[((size_t)bg * Tn + t) * Hn + ug] = h;
        }

        if (t + 1 < Tn) {
            __threadfence();
            __syncthreads();
            // ---- group barrier (monotonic counter, zeroed by reset_kernel) ----
            if (tid == 0) {
                atomicAdd(barp, 1u);
                unsigned target = (unsigned)(t + 1) * NG;
                while (ld_acq(barp) < target) __nanosleep(64);
            }
            __syncthreads();
            // ---- rebuild v = [h(t), x(t+1)]; h via L2 (bypass stale L1) ----
            {
                int bb = tid >> 6;
                int k4 = tid & 63;
                const float4* src = (const float4*)(&g_hbuf[t & 1][b0 + bb][0]);
                float4 hv = __ldcg(src + k4);
                *(float4*)(sV + bb * KP + k4 * 4) = hv;
            }
            if (tid < BPG * In) {
                int bb = tid / In, i = tid % In;
                sV[bb * KP + Hn + i] =
                    x[((size_t)(b0 + bb) * Tn + (t + 1)) * In + i];
            }
            __syncthreads();
        }
    }
}

// Pointwise FC: out[bt][o] = sum_u h[bt][u] * fc_w[o][u] + fc_b[o]
__global__ void __launch_bounds__(256) fc_kernel(
    const float* __restrict__ fc_w,
    const float* __restrict__ fc_b,
    float* __restrict__ out)
{
    extern __shared__ float fsm[];
    float* s_wT = fsm;                 // [Hn][On] transposed fc_w
    float* s_h  = fsm + Hn * On;       // [FCROWS][Hn]
    int tid = threadIdx.x;

    for (int idx = tid; idx < On * Hn; idx += 256) {
        int o = idx / Hn, u = idx % Hn;
        s_wT[u * On + o] = fc_w[idx];
    }
    size_t row0 = (size_t)blockIdx.x * FCROWS;
    for (int idx = tid; idx < FCROWS * (Hn / 4); idx += 256) {
        int r = idx / (Hn / 4), k4 = idx % (Hn / 4);
        *(float4*)(s_h + r * Hn + k4 * 4) =
            *(const float4*)(g_hout + (row0 + r) * Hn + k4 * 4);
    }
    __syncthreads();

    int o  = tid & 31;
    int rg = tid >> 5;                 // 8 row-groups of 4 rows
    float acc0 = fc_b[o], acc1 = acc0, acc2 = acc0, acc3 = acc0;
    const float* h0 = s_h + (rg * 4 + 0) * Hn;
    const float* h1 = s_h + (rg * 4 + 1) * Hn;
    const float* h2 = s_h + (rg * 4 + 2) * Hn;
    const float* h3 = s_h + (rg * 4 + 3) * Hn;
#pragma unroll 8
    for (int u = 0; u < Hn; ++u) {
        float wv = s_wT[u * On + o];
        acc0 = fmaf(h0[u], wv, acc0);
        acc1 = fmaf(h1[u], wv, acc1);
        acc2 = fmaf(h2[u], wv, acc2);
        acc3 = fmaf(h3[u], wv, acc3);
    }
    size_t obase = (row0 + (size_t)rg * 4) * On + o;
    out[obase]          = acc0;
    out[obase + On]     = acc1;
    out[obase + 2 * On] = acc2;
    out[obase + 3 * On] = acc3;
}

extern "C" void kernel_launch(void* const* d_in, const int* in_sizes, int n_in,
                              void* d_out, int out_size) {
    const float* x    = (const float*)d_in[0];
    const float* W_ih = (const float*)d_in[1];
    const float* W_hh = (const float*)d_in[2];
    const float* b_ih = (const float*)d_in[3];
    const float* b_hh = (const float*)d_in[4];
    const float* fc_w = (const float*)d_in[5];
    const float* fc_b = (const float*)d_in[6];
    float* out = (float*)d_out;

    const int lstm_smem = (JPC * KP + BPG * KP + 4 * BPG * UPC + BPG * UPC + JPC) * 4;
    const int fc_smem   = (Hn * On + FCROWS * Hn) * 4;
    cudaFuncSetAttribute(lstm_kernel, cudaFuncAttributeMaxDynamicSharedMemorySize, lstm_smem);
    cudaFuncSetAttribute(fc_kernel,   cudaFuncAttributeMaxDynamicSharedMemorySize, fc_smem);

    reset_kernel<<<1, 512>>>();
    lstm_kernel<<<NB * NG, NTHR, lstm_smem>>>(x, W_ih, W_hh, b_ih, b_hh);
    fc_kernel<<<(Bn * Tn) / FCROWS, 256, fc_smem>>>(fc_w, fc_b, out);
}